// round 2
// baseline (speedup 1.0000x reference)
#include <cuda_runtime.h>
#include <math.h>

#define BDIM   256
#define TILE_B 32
#define OUTN   128
#define INN    128
#define PPAD   132   // 132 % 32 == 4 -> conflict-free strided LDS.128

static constexpr float EPS32     = 1.1920928955078125e-07f;
static constexpr float MIN_ENORM = 1e-15f;
static constexpr float CLAMP_V   = 16.635532333438687f;  // log(2/eps32)
static constexpr float SMOOTHB   = 50.0f;
static constexpr float MAXNORM   = 1.0f - 1e-5f;

// scratch (no cudaMalloc allowed)
__device__ float g_vv[4096];
__device__ float g_uu[OUTN];
__device__ float g_ascale[OUTN];
__device__ float g_ua[OUTN];     // -p . a
__device__ float g_anorm[OUTN];
__device__ float g_coef[OUTN];   // lambda_p * anorm

__device__ __forceinline__ float warp_sum(float v) {
    v += __shfl_xor_sync(0xffffffffu, v, 16);
    v += __shfl_xor_sync(0xffffffffu, v, 8);
    v += __shfl_xor_sync(0xffffffffu, v, 4);
    v += __shfl_xor_sync(0xffffffffu, v, 2);
    v += __shfl_xor_sync(0xffffffffu, v, 1);
    return v;
}

// blocks 0..15: vv[b] = ||x[b]||^2 (warp per row, 32 rows/warp)
// blocks 16..31: per-output constants (warp per o)
__global__ void hyp_pre_kernel(const float* __restrict__ x,
                               const float* __restrict__ w,
                               const float* __restrict__ p) {
    const int wid  = threadIdx.x >> 5;
    const int lane = threadIdx.x & 31;
    if (blockIdx.x < 16) {
        const int base = blockIdx.x * 256 + wid * 32;
        for (int rr = 0; rr < 32; rr++) {
            const int row = base + rr;
            float4 v = reinterpret_cast<const float4*>(x)[row * 32 + lane];
            float s = v.x * v.x + v.y * v.y + v.z * v.z + v.w * v.w;
            s = warp_sum(s);
            if (lane == 0) g_vv[row] = s;
        }
    } else {
        const int o = (blockIdx.x - 16) * 8 + wid;
        float4 pv = reinterpret_cast<const float4*>(p)[o * 32 + lane];
        float4 wv = reinterpret_cast<const float4*>(w)[o * 32 + lane];
        float pp = pv.x * pv.x + pv.y * pv.y + pv.z * pv.z + pv.w * pv.w;
        float ww = wv.x * wv.x + wv.y * wv.y + wv.z * wv.z + wv.w * wv.w;
        float pw = pv.x * wv.x + pv.y * wv.y + pv.z * wv.z + pv.w * wv.w;
        pp = warp_sum(pp);
        ww = warp_sum(ww);
        pw = warp_sum(pw);
        if (lane == 0) {
            const float uu     = pp;
            const float ascale = fmaxf(1.0f - uu, EPS32);   // 2/lambda_bias
            const float anorm  = fmaxf(ascale * sqrtf(ww), MIN_ENORM);
            g_uu[o]     = uu;
            g_ascale[o] = ascale;
            g_ua[o]     = -ascale * pw;
            g_anorm[o]  = anorm;
            g_coef[o]   = (2.0f / fmaxf(1.0f - uu, EPS32)) * anorm;
        }
    }
}

// Main: block = 32 batches x 128 outputs. 256 threads.
// thread t: bq = t>>5 -> rows {bq*4+i}, lane = t&31 -> outputs {lane + 32j}
__global__ __launch_bounds__(BDIM, 1)
void hyp_main_kernel(const float* __restrict__ x,
                     const float* __restrict__ w,
                     const float* __restrict__ p,
                     float* __restrict__ out) {
    extern __shared__ __align__(16) float smem[];
    float* xs = smem;                       // [32][128]
    float* ps = smem + TILE_B * INN;        // [128][PPAD]
    float* ws = ps + OUTN * PPAD;           // [128][PPAD]

    const int tid  = threadIdx.x;
    const int b0   = blockIdx.x * TILE_B;
    const int lane = tid & 31;
    const int bq   = tid >> 5;

    // load x tile (contiguous, coalesced)
    for (int i = tid; i < TILE_B * INN / 4; i += BDIM) {
        reinterpret_cast<float4*>(xs)[i] =
            reinterpret_cast<const float4*>(x)[b0 * (INN / 4) + i];
    }
    // load p, w with row pad (STS consecutive -> conflict-free)
    for (int i = tid; i < OUTN * (INN / 4); i += BDIM) {
        const int o  = i >> 5;
        const int kv = i & 31;
        *reinterpret_cast<float4*>(&ps[o * PPAD + kv * 4]) =
            reinterpret_cast<const float4*>(p)[i];
        *reinterpret_cast<float4*>(&ws[o * PPAD + kv * 4]) =
            reinterpret_cast<const float4*>(w)[i];
    }
    __syncthreads();

    float accP[4][4], accW[4][4];
#pragma unroll
    for (int i = 0; i < 4; i++)
#pragma unroll
        for (int j = 0; j < 4; j++) { accP[i][j] = 0.0f; accW[i][j] = 0.0f; }

#pragma unroll 2
    for (int k = 0; k < INN; k += 4) {
        float4 xv[4];
#pragma unroll
        for (int i = 0; i < 4; i++)
            xv[i] = *reinterpret_cast<const float4*>(&xs[(bq * 4 + i) * INN + k]);
        float4 pr[4], wr[4];
#pragma unroll
        for (int j = 0; j < 4; j++) {
            const int o = lane + 32 * j;
            pr[j] = *reinterpret_cast<const float4*>(&ps[o * PPAD + k]);
            wr[j] = *reinterpret_cast<const float4*>(&ws[o * PPAD + k]);
        }
#pragma unroll
        for (int i = 0; i < 4; i++) {
#pragma unroll
            for (int j = 0; j < 4; j++) {
                accP[i][j] += xv[i].x * pr[j].x;
                accP[i][j] += xv[i].y * pr[j].y;
                accP[i][j] += xv[i].z * pr[j].z;
                accP[i][j] += xv[i].w * pr[j].w;
                accW[i][j] += xv[i].x * wr[j].x;
                accW[i][j] += xv[i].y * wr[j].y;
                accW[i][j] += xv[i].z * wr[j].z;
                accW[i][j] += xv[i].w * wr[j].w;
            }
        }
    }

    // per-o constants (hoisted)
    float uuv[4], asc[4], uav[4], anv[4], cfv[4];
#pragma unroll
    for (int j = 0; j < 4; j++) {
        const int o = lane + 32 * j;
        uuv[j] = g_uu[o];
        asc[j] = g_ascale[o];
        uav[j] = g_ua[o];
        anv[j] = g_anorm[o];
        cfv[j] = g_coef[o];
    }

#pragma unroll
    for (int i = 0; i < 4; i++) {
        const int b  = b0 + bq * 4 + i;
        const float vv = g_vv[b];
#pragma unroll
        for (int j = 0; j < 4; j++) {
            const int o = lane + 32 * j;
            const float pv = accP[i][j];
            const float av = asc[j] * accW[i][j];

            const float alpha = 1.0f - 2.0f * pv + vv;
            const float beta  = 1.0f - uuv[j];
            const float den   = fmaxf(1.0f - 2.0f * pv + uuv[j] * vv, EPS32);
            const float inv_den = 1.0f / den;

            float suba   = (alpha * uav[j] + beta * av) * inv_den;
            float sub_sq = (alpha * alpha * uuv[j]
                            - 2.0f * alpha * beta * pv
                            + beta * beta * vv) * (inv_den * inv_den);

            // project onto ball
            const float nrm = fmaxf(sqrtf(sub_sq), MIN_ENORM);
            if (nrm > MAXNORM) {
                const float s = MAXNORM / nrm;
                suba  *= s;
                sub_sq = MAXNORM * MAXNORM;
            }

            const float lam = 2.0f / fmaxf(1.0f - sub_sq, EPS32);
            float arg = lam * suba / anv[j];

            // smooth clamp to [-CLAMP_V, CLAMP_V], beta = 50
            const float z1  = SMOOTHB * (arg + CLAMP_V);
            const float z2  = SMOOTHB * (arg - CLAMP_V);
            const float sp1 = fmaxf(z1, 0.0f) + log1pf(expf(-fabsf(z1)));
            const float sp2 = fmaxf(z2, 0.0f) + log1pf(expf(-fabsf(z2)));
            const float sc  = -CLAMP_V + (sp1 - sp2) / SMOOTHB;

            out[b * OUTN + o] = cfv[j] * asinhf(sc);
        }
    }
}

extern "C" void kernel_launch(void* const* d_in, const int* in_sizes, int n_in,
                              void* d_out, int out_size) {
    const float* x = (const float*)d_in[0];   // [4096, 128]
    const float* w = (const float*)d_in[1];   // [128, 128] weight
    const float* p = (const float*)d_in[2];   // [128, 128] bias
    float* out = (float*)d_out;               // [4096, 128]

    const int smem_bytes = (TILE_B * INN + 2 * OUTN * PPAD) * 4;  // 151552
    cudaFuncSetAttribute(hyp_main_kernel,
                         cudaFuncAttributeMaxDynamicSharedMemorySize, smem_bytes);

    hyp_pre_kernel<<<32, 256>>>(x, w, p);
    hyp_main_kernel<<<4096 / TILE_B, BDIM, smem_bytes>>>(x, w, p, out);
}

// round 4
// speedup vs baseline: 1.1599x; 1.1599x over previous
#include <cuda_runtime.h>
#include <math.h>

#define OUTN   128
#define INN    128
#define TILE_B 32
#define OTILE  64
#define PPAD   132   // weight row stride: 4*lane%32 pattern -> conflict-free LDS.128

static constexpr float EPS32     = 1.1920928955078125e-07f;
static constexpr float MIN_ENORM = 1e-15f;
static constexpr float CLAMP_V   = 16.635532333438687f;  // log(2/eps32)
static constexpr float SMOOTHB   = 50.0f;
static constexpr float MAXNORM   = 1.0f - 1e-5f;

// ---- scratch (no cudaMalloc allowed) ----
__device__ float g_vv[4096];
__device__ float g_uu[OUTN];
__device__ float g_ascale[OUTN];
__device__ float g_ua[OUTN];       // -p . a
__device__ float g_ranorm[OUTN];   // 1/anorm
__device__ float g_coef[OUTN];     // lambda_p * anorm
__device__ float g_xt[4096 * 128]; // x transposed per 32-batch tile: [bb][k][b_local]

// ---------------- helpers ----------------
__device__ __forceinline__ float warp_sum(float v) {
    v += __shfl_xor_sync(0xffffffffu, v, 16);
    v += __shfl_xor_sync(0xffffffffu, v, 8);
    v += __shfl_xor_sync(0xffffffffu, v, 4);
    v += __shfl_xor_sync(0xffffffffu, v, 2);
    v += __shfl_xor_sync(0xffffffffu, v, 1);
    return v;
}

__device__ __forceinline__ void ffma2(unsigned long long& acc,
                                      unsigned long long a,
                                      unsigned long long b) {
    asm("fma.rn.f32x2 %0, %1, %2, %0;" : "+l"(acc) : "l"(a), "l"(b));
}

__device__ __forceinline__ unsigned long long dup2(float v) {
    unsigned long long r;
    unsigned u = __float_as_uint(v);
    asm("mov.b64 %0, {%1, %1};" : "=l"(r) : "r"(u));
    return r;
}

__device__ __forceinline__ float pair_lo(unsigned long long v) {
    return __uint_as_float((unsigned)(v & 0xffffffffull));
}
__device__ __forceinline__ float pair_hi(unsigned long long v) {
    return __uint_as_float((unsigned)(v >> 32));
}

__device__ __forceinline__ float comp4(float4 v, int kk) {
    switch (kk) { case 0: return v.x; case 1: return v.y; case 2: return v.z; default: return v.w; }
}

// ---------------- pre-kernel ----------------
// blocks 0..15   : vv[b] = ||x[b]||^2
// blocks 16..31  : per-output constants
// blocks 32..159 : transpose x into g_xt [bb][k][b_local]
__global__ void hyp_pre_kernel(const float* __restrict__ x,
                               const float* __restrict__ w,
                               const float* __restrict__ p) {
    __shared__ float tile[32][129];
    const int tid  = threadIdx.x;
    const int wid  = tid >> 5;
    const int lane = tid & 31;

    if (blockIdx.x < 16) {
        const int base = blockIdx.x * 256 + wid * 32;
        for (int rr = 0; rr < 32; rr++) {
            const int row = base + rr;
            float4 v = reinterpret_cast<const float4*>(x)[row * 32 + lane];
            float s = v.x * v.x + v.y * v.y + v.z * v.z + v.w * v.w;
            s = warp_sum(s);
            if (lane == 0) g_vv[row] = s;
        }
    } else if (blockIdx.x < 32) {
        const int o = (blockIdx.x - 16) * 8 + wid;
        float4 pv = reinterpret_cast<const float4*>(p)[o * 32 + lane];
        float4 wv = reinterpret_cast<const float4*>(w)[o * 32 + lane];
        float pp = pv.x * pv.x + pv.y * pv.y + pv.z * pv.z + pv.w * pv.w;
        float ww = wv.x * wv.x + wv.y * wv.y + wv.z * wv.z + wv.w * wv.w;
        float pw = pv.x * wv.x + pv.y * wv.y + pv.z * wv.z + pv.w * wv.w;
        pp = warp_sum(pp);
        ww = warp_sum(ww);
        pw = warp_sum(pw);
        if (lane == 0) {
            const float uu     = pp;
            const float ascale = fmaxf(1.0f - uu, EPS32);   // 2/lambda_bias
            const float anorm  = fmaxf(ascale * sqrtf(ww), MIN_ENORM);
            g_uu[o]     = uu;
            g_ascale[o] = ascale;
            g_ua[o]     = -ascale * pw;
            g_ranorm[o] = 1.0f / anorm;
            g_coef[o]   = (2.0f / fmaxf(1.0f - uu, EPS32)) * anorm;
        }
    } else {
        // transpose one 32x128 x tile
        const int bb = blockIdx.x - 32;
        for (int i = tid; i < 1024; i += 256) {           // 1024 float4 in
            const int b  = i >> 5;
            const int kv = i & 31;
            float4 v = reinterpret_cast<const float4*>(x)[bb * 1024 + i];
            tile[b][4 * kv + 0] = v.x;
            tile[b][4 * kv + 1] = v.y;
            tile[b][4 * kv + 2] = v.z;
            tile[b][4 * kv + 3] = v.w;
        }
        __syncthreads();
        for (int f = tid; f < 1024; f += 256) {           // 1024 float4 out
            const int k = f >> 3;
            const int j = f & 7;                           // covers b = 4j..4j+3
            float4 v;
            v.x = tile[4 * j + 0][k];
            v.y = tile[4 * j + 1][k];
            v.z = tile[4 * j + 2][k];
            v.w = tile[4 * j + 3][k];
            reinterpret_cast<float4*>(g_xt)[bb * 1024 + k * 8 + j] = v;
        }
    }
}

// ---------------- epilogue math ----------------
__device__ __forceinline__ float epilogue(float pv, float wacc, float vv,
                                          float uu, float asc, float ua,
                                          float ranorm, float coef) {
    const float av      = asc * wacc;
    const float alpha   = 1.0f - 2.0f * pv + vv;
    const float beta    = 1.0f - uu;
    const float den     = fmaxf(1.0f - 2.0f * pv + uu * vv, EPS32);
    const float inv_den = __fdividef(1.0f, den);

    float suba   = (alpha * ua + beta * av) * inv_den;
    float sub_sq = (alpha * alpha * uu - 2.0f * alpha * beta * pv + beta * beta * vv)
                   * (inv_den * inv_den);

    const float nrm = fmaxf(sqrtf(sub_sq), MIN_ENORM);
    if (nrm > MAXNORM) {
        const float s = __fdividef(MAXNORM, nrm);
        suba  *= s;
        sub_sq = MAXNORM * MAXNORM;
    }

    const float lam = __fdividef(2.0f, fmaxf(1.0f - sub_sq, EPS32));
    const float arg = lam * suba * ranorm;

    float sc;
    if (fabsf(arg) < 16.0f) {
        sc = arg;  // smooth clamp is identity to <1e-14 here
    } else {
        const float z1  = SMOOTHB * (arg + CLAMP_V);
        const float z2  = SMOOTHB * (arg - CLAMP_V);
        const float sp1 = fmaxf(z1, 0.0f) + log1pf(__expf(-fabsf(z1)));
        const float sp2 = fmaxf(z2, 0.0f) + log1pf(__expf(-fabsf(z2)));
        sc = -CLAMP_V + (sp1 - sp2) * (1.0f / SMOOTHB);
    }

    const float s_ = fabsf(sc);
    const float r  = __logf(s_ + sqrtf(fmaf(s_, s_, 1.0f)));   // asinh(|sc|)
    return coef * copysignf(r, sc);
}

// ---------------- main kernel ----------------
// grid (2, 128): x = out-block (64 outputs), y = batch-block (32 batches)
// 128 threads. Warp w -> batches w*8..w*8+7 (as 4 pairs). Lane -> outputs {l, l+32}.
__global__ __launch_bounds__(128)
void hyp_main_kernel(const float* __restrict__ w,
                     const float* __restrict__ p,
                     float* __restrict__ out) {
    extern __shared__ __align__(16) float smem[];
    float* ws = smem;                  // [128][PPAD]: rows 0..63 = p slice, 64..127 = w slice
    float* xt = smem + 128 * PPAD;     // [128 k][32 b]

    const int tid  = threadIdx.x;
    const int lane = tid & 31;
    const int wid  = tid >> 5;
    const int ob   = blockIdx.x;       // 0,1
    const int bb   = blockIdx.y;       // 0..127

    // load weight tiles (o-major, padded rows)
    for (int i = tid; i < 128 * 32; i += 128) {
        const int r  = i >> 5;
        const int kv = i & 31;
        float4 v;
        if (r < 64) v = reinterpret_cast<const float4*>(p)[(ob * 64 + r) * 32 + kv];
        else        v = reinterpret_cast<const float4*>(w)[(ob * 64 + r - 64) * 32 + kv];
        *reinterpret_cast<float4*>(&ws[r * PPAD + 4 * kv]) = v;
    }
    // load transposed x tile (contiguous copy)
    for (int i = tid; i < 1024; i += 128) {
        reinterpret_cast<float4*>(xt)[i] =
            reinterpret_cast<const float4*>(g_xt)[bb * 1024 + i];
    }
    __syncthreads();

    unsigned long long aP[4][2], aW[4][2];
#pragma unroll
    for (int i = 0; i < 4; i++) { aP[i][0] = 0; aP[i][1] = 0; aW[i][0] = 0; aW[i][1] = 0; }

    const float* prow0 = ws + lane * PPAD;
    const float* prow1 = ws + (lane + 32) * PPAD;
    const float* wrow0 = ws + (lane + 64) * PPAD;
    const float* wrow1 = ws + (lane + 96) * PPAD;
    const float* xbase = xt + wid * 8;

#pragma unroll 4
    for (int k = 0; k < INN; k += 4) {
        const float4 p0 = *reinterpret_cast<const float4*>(prow0 + k);
        const float4 p1 = *reinterpret_cast<const float4*>(prow1 + k);
        const float4 w0 = *reinterpret_cast<const float4*>(wrow0 + k);
        const float4 w1 = *reinterpret_cast<const float4*>(wrow1 + k);
#pragma unroll
        for (int kk = 0; kk < 4; kk++) {
            const float* xr = xbase + (k + kk) * 32;
            const ulonglong2 xa = *reinterpret_cast<const ulonglong2*>(xr);      // pairs (0,1),(2,3)
            const ulonglong2 xb = *reinterpret_cast<const ulonglong2*>(xr + 4);  // pairs (4,5),(6,7)
            const unsigned long long dp0 = dup2(comp4(p0, kk));
            const unsigned long long dp1 = dup2(comp4(p1, kk));
            const unsigned long long dw0 = dup2(comp4(w0, kk));
            const unsigned long long dw1 = dup2(comp4(w1, kk));
            ffma2(aP[0][0], xa.x, dp0); ffma2(aP[0][1], xa.x, dp1);
            ffma2(aW[0][0], xa.x, dw0); ffma2(aW[0][1], xa.x, dw1);
            ffma2(aP[1][0], xa.y, dp0); ffma2(aP[1][1], xa.y, dp1);
            ffma2(aW[1][0], xa.y, dw0); ffma2(aW[1][1], xa.y, dw1);
            ffma2(aP[2][0], xb.x, dp0); ffma2(aP[2][1], xb.x, dp1);
            ffma2(aW[2][0], xb.x, dw0); ffma2(aW[2][1], xb.x, dw1);
            ffma2(aP[3][0], xb.y, dp0); ffma2(aP[3][1], xb.y, dp1);
            ffma2(aW[3][0], xb.y, dw0); ffma2(aW[3][1], xb.y, dw1);
        }
    }

    // per-o constants
    const int og0 = ob * 64 + lane;
    const int og1 = og0 + 32;
    const float uu0 = g_uu[og0],     uu1 = g_uu[og1];
    const float as0 = g_ascale[og0], as1 = g_ascale[og1];
    const float ua0 = g_ua[og0],     ua1 = g_ua[og1];
    const float rn0 = g_ranorm[og0], rn1 = g_ranorm[og1];
    const float cf0 = g_coef[og0],   cf1 = g_coef[og1];

#pragma unroll
    for (int bp = 0; bp < 4; bp++) {
        const int b_even = bb * 32 + wid * 8 + bp * 2;
        const float vv0 = g_vv[b_even];
        const float vv1 = g_vv[b_even + 1];

        out[b_even * OUTN + og0] =
            epilogue(pair_lo(aP[bp][0]), pair_lo(aW[bp][0]), vv0, uu0, as0, ua0, rn0, cf0);
        out[b_even * OUTN + og1] =
            epilogue(pair_lo(aP[bp][1]), pair_lo(aW[bp][1]), vv0, uu1, as1, ua1, rn1, cf1);
        out[(b_even + 1) * OUTN + og0] =
            epilogue(pair_hi(aP[bp][0]), pair_hi(aW[bp][0]), vv1, uu0, as0, ua0, rn0, cf0);
        out[(b_even + 1) * OUTN + og1] =
            epilogue(pair_hi(aP[bp][1]), pair_hi(aW[bp][1]), vv1, uu1, as1, ua1, rn1, cf1);
    }
}

extern "C" void kernel_launch(void* const* d_in, const int* in_sizes, int n_in,
                              void* d_out, int out_size) {
    const float* x = (const float*)d_in[0];   // [4096, 128]
    const float* w = (const float*)d_in[1];   // [128, 128] weight
    const float* p = (const float*)d_in[2];   // [128, 128] bias
    float* out = (float*)d_out;               // [4096, 128]

    const int smem_bytes = (128 * PPAD + 128 * 32) * 4;  // 83968
    cudaFuncSetAttribute(hyp_main_kernel,
                         cudaFuncAttributeMaxDynamicSharedMemorySize, smem_bytes);

    hyp_pre_kernel<<<160, 256>>>(x, w, p);
    dim3 grid(2, 128);
    hyp_main_kernel<<<grid, 128, smem_bytes>>>(w, p, out);
}

// round 6
// speedup vs baseline: 1.5275x; 1.3168x over previous
#include <cuda_runtime.h>
#include <cuda_bf16.h>
#include <math.h>
#include <cstdint>

static constexpr float EPS32     = 1.1920928955078125e-07f;
static constexpr float MIN_ENORM = 1e-15f;
static constexpr float CLAMP_V   = 16.635532333438687f;  // log(2/eps32)
static constexpr float SMOOTHB   = 50.0f;
static constexpr float MAXNORM   = 1.0f - 1e-5f;

// ---- smem layout (bytes from dynamic-smem base) ----
// A: 64 rows x 136 bf16 (stride 272B). B: 128 rows x 136 bf16.
#define A_HI_OFF   0u
#define A_LO_OFF   17408u
#define B_HI_OFF   34816u
#define B_LO_OFF   69632u
#define VVS_OFF    104448u
#define C_UU_OFF   104704u
#define C_AS_OFF   104960u
#define C_UA_OFF   105216u
#define C_RN_OFF   105472u
#define C_CF_OFF   105728u
#define SMEM_BYTES 105984

__device__ __forceinline__ uint32_t smem_to_u32(const void* smem_ptr) {
    uint32_t addr;
    asm("{ .reg .u64 tmp; cvta.to.shared.u64 tmp, %1; cvt.u32.u64 %0, tmp; }"
        : "=r"(addr) : "l"(smem_ptr));
    return addr;
}

__device__ __forceinline__ void ldsm4(uint32_t addr, uint32_t r[4]) {
    asm volatile("ldmatrix.sync.aligned.m8n8.x4.shared.b16 {%0,%1,%2,%3}, [%4];"
                 : "=r"(r[0]), "=r"(r[1]), "=r"(r[2]), "=r"(r[3]) : "r"(addr));
}

__device__ __forceinline__ void mma16816(float c[4], const uint32_t a[4],
                                         uint32_t b0, uint32_t b1) {
    asm volatile(
        "mma.sync.aligned.m16n8k16.row.col.f32.bf16.bf16.f32 "
        "{%0,%1,%2,%3}, {%4,%5,%6,%7}, {%8,%9}, {%0,%1,%2,%3};"
        : "+f"(c[0]), "+f"(c[1]), "+f"(c[2]), "+f"(c[3])
        : "r"(a[0]), "r"(a[1]), "r"(a[2]), "r"(a[3]), "r"(b0), "r"(b1));
}

__device__ __forceinline__ float warp_sum(float v) {
    v += __shfl_xor_sync(0xffffffffu, v, 16);
    v += __shfl_xor_sync(0xffffffffu, v, 8);
    v += __shfl_xor_sync(0xffffffffu, v, 4);
    v += __shfl_xor_sync(0xffffffffu, v, 2);
    v += __shfl_xor_sync(0xffffffffu, v, 1);
    return v;
}

// split float4 -> 4 bf16 hi (8B) + 4 bf16 lo (8B)
__device__ __forceinline__ void store_split8(char* hi, char* lo, uint32_t off, float4 v) {
    __nv_bfloat16 h0 = __float2bfloat16(v.x);
    __nv_bfloat16 h1 = __float2bfloat16(v.y);
    __nv_bfloat16 h2 = __float2bfloat16(v.z);
    __nv_bfloat16 h3 = __float2bfloat16(v.w);
    __nv_bfloat16 l0 = __float2bfloat16(v.x - __bfloat162float(h0));
    __nv_bfloat16 l1 = __float2bfloat16(v.y - __bfloat162float(h1));
    __nv_bfloat16 l2 = __float2bfloat16(v.z - __bfloat162float(h2));
    __nv_bfloat16 l3 = __float2bfloat16(v.w - __bfloat162float(h3));
    uint2 hv, lv;
    hv.x = (uint32_t)*(unsigned short*)&h0 | ((uint32_t)*(unsigned short*)&h1 << 16);
    hv.y = (uint32_t)*(unsigned short*)&h2 | ((uint32_t)*(unsigned short*)&h3 << 16);
    lv.x = (uint32_t)*(unsigned short*)&l0 | ((uint32_t)*(unsigned short*)&l1 << 16);
    lv.y = (uint32_t)*(unsigned short*)&l2 | ((uint32_t)*(unsigned short*)&l3 << 16);
    *reinterpret_cast<uint2*>(hi + off) = hv;
    *reinterpret_cast<uint2*>(lo + off) = lv;
}

// ---------------- epilogue math (validated, rel_err 3.3e-6 baseline) ----------------
__device__ __forceinline__ float epilogue(float pv, float wacc, float vv,
                                          float uu, float asc, float ua,
                                          float ranorm, float coef) {
    const float av      = asc * wacc;
    const float alpha   = 1.0f - 2.0f * pv + vv;
    const float beta    = 1.0f - uu;
    const float den     = fmaxf(1.0f - 2.0f * pv + uu * vv, EPS32);
    const float inv_den = __fdividef(1.0f, den);

    float suba   = (alpha * ua + beta * av) * inv_den;
    float sub_sq = (alpha * alpha * uu - 2.0f * alpha * beta * pv + beta * beta * vv)
                   * (inv_den * inv_den);

    const float nrm = fmaxf(sqrtf(sub_sq), MIN_ENORM);
    if (nrm > MAXNORM) {
        const float s = __fdividef(MAXNORM, nrm);
        suba  *= s;
        sub_sq = MAXNORM * MAXNORM;
    }

    const float lam = __fdividef(2.0f, fmaxf(1.0f - sub_sq, EPS32));
    const float arg = lam * suba * ranorm;

    float sc;
    if (fabsf(arg) < 16.0f) {
        sc = arg;  // smooth clamp is identity to <1e-14 here
    } else {
        const float z1  = SMOOTHB * (arg + CLAMP_V);
        const float z2  = SMOOTHB * (arg - CLAMP_V);
        const float sp1 = fmaxf(z1, 0.0f) + log1pf(__expf(-fabsf(z1)));
        const float sp2 = fmaxf(z2, 0.0f) + log1pf(__expf(-fabsf(z2)));
        sc = -CLAMP_V + (sp1 - sp2) * (1.0f / SMOOTHB);
    }

    const float s_ = fabsf(sc);
    const float r  = __logf(s_ + sqrtf(fmaf(s_, s_, 1.0f)));   // asinh(|sc|)
    return coef * copysignf(r, sc);
}

// ---------------- fused kernel ----------------
// grid (2, 64): ob = 64-output slice, bb = 64-batch tile. 256 threads = 8 warps.
// Warp w: m-tile (w&3)*16 (16 batches), n-range (w>>2)*32 (32 outputs, P and W).
__global__ __launch_bounds__(256)
void hyp_mma_kernel(const float* __restrict__ x,
                    const float* __restrict__ w,
                    const float* __restrict__ p,
                    float* __restrict__ out) {
    extern __shared__ __align__(16) char sm[];
    const uint32_t sbase = smem_to_u32(sm);

    const int tid  = threadIdx.x;
    const int wid  = tid >> 5;
    const int lane = tid & 31;
    const int ob   = blockIdx.x;   // 0..1
    const int bb   = blockIdx.y;   // 0..63

    float* vvs = reinterpret_cast<float*>(sm + VVS_OFF);
    float* cU  = reinterpret_cast<float*>(sm + C_UU_OFF);
    float* cAs = reinterpret_cast<float*>(sm + C_AS_OFF);
    float* cUa = reinterpret_cast<float*>(sm + C_UA_OFF);
    float* cRn = reinterpret_cast<float*>(sm + C_RN_OFF);
    float* cCf = reinterpret_cast<float*>(sm + C_CF_OFF);

    // ---- prologue A: x tile [64][128], bf16-split, fused vv ----
    {
        const int row = tid >> 2;        // 0..63
        const int q   = tid & 3;         // 32-elem chunk
        const float* src = x + (size_t)(bb * 64 + row) * 128 + q * 32;
        char* hi = sm + A_HI_OFF;
        char* lo = sm + A_LO_OFF;
        float ss = 0.0f;
#pragma unroll
        for (int i = 0; i < 8; i++) {
            float4 v = reinterpret_cast<const float4*>(src)[i];
            ss += v.x * v.x + v.y * v.y + v.z * v.z + v.w * v.w;
            store_split8(hi, lo, (uint32_t)(row * 272 + (q * 32 + i * 4) * 2), v);
        }
        ss += __shfl_xor_sync(0xffffffffu, ss, 1);
        ss += __shfl_xor_sync(0xffffffffu, ss, 2);
        if (q == 0) vvs[row] = ss;
    }
    // ---- prologue B: [p slice; w slice] [128][128], bf16-split ----
    {
        const int row = tid >> 1;        // 0..127
        const int q   = tid & 1;
        const float* src = (row < 64)
            ? (p + (size_t)(ob * 64 + row) * 128 + q * 64)
            : (w + (size_t)(ob * 64 + row - 64) * 128 + q * 64);
        char* hi = sm + B_HI_OFF;
        char* lo = sm + B_LO_OFF;
#pragma unroll
        for (int i = 0; i < 16; i++) {
            float4 v = reinterpret_cast<const float4*>(src)[i];
            store_split8(hi, lo, (uint32_t)(row * 272 + (q * 64 + i * 4) * 2), v);
        }
    }
    // ---- per-o constants: warp wid computes o_local = wid*8 .. wid*8+7 ----
    {
#pragma unroll
        for (int r = 0; r < 8; r++) {
            const int ol = wid * 8 + r;
            const int og = ob * 64 + ol;
            float4 pv4 = reinterpret_cast<const float4*>(p + (size_t)og * 128)[lane];
            float4 wv4 = reinterpret_cast<const float4*>(w + (size_t)og * 128)[lane];
            float pp = pv4.x * pv4.x + pv4.y * pv4.y + pv4.z * pv4.z + pv4.w * pv4.w;
            float ww = wv4.x * wv4.x + wv4.y * wv4.y + wv4.z * wv4.z + wv4.w * wv4.w;
            float pw = pv4.x * wv4.x + pv4.y * wv4.y + pv4.z * wv4.z + pv4.w * wv4.w;
            pp = warp_sum(pp);
            ww = warp_sum(ww);
            pw = warp_sum(pw);
            if (lane == 0) {
                const float uu     = pp;
                const float ascale = fmaxf(1.0f - uu, EPS32);   // 2/lambda_bias
                const float anorm  = fmaxf(ascale * sqrtf(ww), MIN_ENORM);
                cU[ol]  = uu;
                cAs[ol] = ascale;
                cUa[ol] = -ascale * pw;
                cRn[ol] = 1.0f / anorm;
                cCf[ol] = (2.0f / fmaxf(1.0f - uu, EPS32)) * anorm;
            }
        }
    }
    __syncthreads();

    // ---- ldmatrix address prep ----
    const int r8   = (lane & 7) + ((lane >> 3) & 1) * 8;   // row within 16-row tile
    const int koff = (lane >> 4) * 8;                       // k half (0/8)
    const uint32_t aOff = (uint32_t)(((wid & 3) * 16 + r8) * 272 + koff * 2);
    const int nb = (wid >> 2) * 32;
    const uint32_t bp0 = (uint32_t)((nb +  0 + r8) * 272 + koff * 2);
    const uint32_t bp1 = (uint32_t)((nb + 16 + r8) * 272 + koff * 2);
    const uint32_t bw0 = (uint32_t)((nb + 64 + r8) * 272 + koff * 2);
    const uint32_t bw1 = (uint32_t)((nb + 80 + r8) * 272 + koff * 2);

    float accP[4][4], accW[4][4];
#pragma unroll
    for (int j = 0; j < 4; j++)
#pragma unroll
        for (int c = 0; c < 4; c++) { accP[j][c] = 0.0f; accW[j][c] = 0.0f; }

    // ---- mainloop: 3 split terms (hi*hi, hi*lo, lo*hi), 8 k-steps each ----
#pragma unroll
    for (int term = 0; term < 3; term++) {
        const uint32_t aBase = sbase + (term == 2 ? A_LO_OFF : A_HI_OFF);
        const uint32_t bBase = sbase + (term == 1 ? B_LO_OFF : B_HI_OFF);
#pragma unroll
        for (int ks = 0; ks < 8; ks++) {
            const uint32_t kb = (uint32_t)ks * 32u;
            uint32_t a[4];
            ldsm4(aBase + aOff + kb, a);
            uint32_t b0[4], b1[4], b2[4], b3[4];
            ldsm4(bBase + bp0 + kb, b0);
            ldsm4(bBase + bp1 + kb, b1);
            ldsm4(bBase + bw0 + kb, b2);
            ldsm4(bBase + bw1 + kb, b3);
            mma16816(accP[0], a, b0[0], b0[2]);
            mma16816(accP[1], a, b0[1], b0[3]);
            mma16816(accP[2], a, b1[0], b1[2]);
            mma16816(accP[3], a, b1[1], b1[3]);
            mma16816(accW[0], a, b2[0], b2[2]);
            mma16816(accW[1], a, b2[1], b2[3]);
            mma16816(accW[2], a, b3[0], b3[2]);
            mma16816(accW[3], a, b3[1], b3[3]);
        }
    }

    // ---- epilogue: thread holds D rows m0, m0+8; cols q*2, q*2+1 per n8 tile ----
    {
        const int m0 = (wid & 3) * 16 + (lane >> 2);
        const int q  = lane & 3;
        const float vv0 = vvs[m0];
        const float vv1 = vvs[m0 + 8];
        const size_t bG0 = (size_t)(bb * 64 + m0) * 128;
        const size_t bG1 = (size_t)(bb * 64 + m0 + 8) * 128;
#pragma unroll
        for (int j = 0; j < 4; j++) {
            const int ol0 = nb + j * 8 + q * 2;
            const int ol1 = ol0 + 1;
            const int og0 = ob * 64 + ol0;
            const float u0 = cU[ol0],  u1 = cU[ol1];
            const float s0 = cAs[ol0], s1 = cAs[ol1];
            const float a0 = cUa[ol0], a1 = cUa[ol1];
            const float r0 = cRn[ol0], r1 = cRn[ol1];
            const float f0 = cCf[ol0], f1 = cCf[ol1];

            float2 e0, e1;
            e0.x = epilogue(accP[j][0], accW[j][0], vv0, u0, s0, a0, r0, f0);
            e0.y = epilogue(accP[j][1], accW[j][1], vv0, u1, s1, a1, r1, f1);
            e1.x = epilogue(accP[j][2], accW[j][2], vv1, u0, s0, a0, r0, f0);
            e1.y = epilogue(accP[j][3], accW[j][3], vv1, u1, s1, a1, r1, f1);

            *reinterpret_cast<float2*>(out + bG0 + og0) = e0;
            *reinterpret_cast<float2*>(out + bG1 + og0) = e1;
        }
    }
}

extern "C" void kernel_launch(void* const* d_in, const int* in_sizes, int n_in,
                              void* d_out, int out_size) {
    const float* x = (const float*)d_in[0];   // [4096, 128]
    const float* w = (const float*)d_in[1];   // [128, 128] weight
    const float* p = (const float*)d_in[2];   // [128, 128] bias
    float* out = (float*)d_out;               // [4096, 128]

    cudaFuncSetAttribute(hyp_mma_kernel,
                         cudaFuncAttributeMaxDynamicSharedMemorySize, SMEM_BYTES);
    dim3 grid(2, 64);
    hyp_mma_kernel<<<grid, 256, SMEM_BYTES>>>(x, w, p, out);
}

// round 8
// speedup vs baseline: 1.6257x; 1.0643x over previous
#include <cuda_runtime.h>
#include <cuda_bf16.h>
#include <math.h>
#include <cstdint>

static constexpr float EPS32     = 1.1920928955078125e-07f;
static constexpr float MIN_ENORM = 1e-15f;
static constexpr float CLAMP_V   = 16.635532333438687f;  // log(2/eps32)
static constexpr float SMOOTHB   = 50.0f;
static constexpr float MAXNORM   = 1.0f - 1e-5f;

// ---- smem layout (bytes from dynamic-smem base) ----
// A: 64 rows x 136 bf16 (stride 272B). B: 128 rows x 136 bf16.
#define A_HI_OFF   0u
#define A_LO_OFF   17408u
#define B_HI_OFF   34816u
#define B_LO_OFF   69632u
#define VVS_OFF    104448u
#define C_UU_OFF   104704u
#define C_AS_OFF   104960u
#define C_UA_OFF   105216u
#define C_RN_OFF   105472u
#define C_CF_OFF   105728u
#define SMEM_BYTES 105984

__device__ __forceinline__ uint32_t smem_to_u32(const void* smem_ptr) {
    uint32_t addr;
    asm("{ .reg .u64 tmp; cvta.to.shared.u64 tmp, %1; cvt.u32.u64 %0, tmp; }"
        : "=r"(addr) : "l"(smem_ptr));
    return addr;
}

__device__ __forceinline__ void ldsm4(uint32_t addr, uint32_t r[4]) {
    asm volatile("ldmatrix.sync.aligned.m8n8.x4.shared.b16 {%0,%1,%2,%3}, [%4];"
                 : "=r"(r[0]), "=r"(r[1]), "=r"(r[2]), "=r"(r[3]) : "r"(addr));
}

__device__ __forceinline__ void mma16816(float c[4], const uint32_t a[4],
                                         uint32_t b0, uint32_t b1) {
    asm volatile(
        "mma.sync.aligned.m16n8k16.row.col.f32.bf16.bf16.f32 "
        "{%0,%1,%2,%3}, {%4,%5,%6,%7}, {%8,%9}, {%0,%1,%2,%3};"
        : "+f"(c[0]), "+f"(c[1]), "+f"(c[2]), "+f"(c[3])
        : "r"(a[0]), "r"(a[1]), "r"(a[2]), "r"(a[3]), "r"(b0), "r"(b1));
}

// packed split: float4 -> 4 bf16 hi (8B) + 4 bf16 lo (8B), bf16x2 CVTs
__device__ __forceinline__ void store_split8(char* hi, char* lo, uint32_t off, float4 v) {
    uint32_t h01, h23;
    asm("cvt.rn.bf16x2.f32 %0, %1, %2;" : "=r"(h01) : "f"(v.y), "f"(v.x));
    asm("cvt.rn.bf16x2.f32 %0, %1, %2;" : "=r"(h23) : "f"(v.w), "f"(v.z));
    const float fx = __uint_as_float(h01 << 16);
    const float fy = __uint_as_float(h01 & 0xffff0000u);
    const float fz = __uint_as_float(h23 << 16);
    const float fw = __uint_as_float(h23 & 0xffff0000u);
    uint32_t l01, l23;
    asm("cvt.rn.bf16x2.f32 %0, %1, %2;" : "=r"(l01) : "f"(v.y - fy), "f"(v.x - fx));
    asm("cvt.rn.bf16x2.f32 %0, %1, %2;" : "=r"(l23) : "f"(v.w - fw), "f"(v.z - fz));
    uint2 hv, lv;
    hv.x = h01; hv.y = h23;
    lv.x = l01; lv.y = l23;
    *reinterpret_cast<uint2*>(hi + off) = hv;
    *reinterpret_cast<uint2*>(lo + off) = lv;
}

// ---------------- epilogue math (validated) ----------------
__device__ __forceinline__ float epilogue(float pv, float wacc, float vv,
                                          float uu, float asc, float ua,
                                          float ranorm, float coef) {
    const float av      = asc * wacc;
    const float alpha   = 1.0f - 2.0f * pv + vv;
    const float beta    = 1.0f - uu;
    const float den     = fmaxf(1.0f - 2.0f * pv + uu * vv, EPS32);
    const float inv_den = __fdividef(1.0f, den);

    float suba   = (alpha * ua + beta * av) * inv_den;
    float sub_sq = (alpha * alpha * uu - 2.0f * alpha * beta * pv + beta * beta * vv)
                   * (inv_den * inv_den);

    const float nrm = fmaxf(sqrtf(sub_sq), MIN_ENORM);
    if (nrm > MAXNORM) {
        const float s = __fdividef(MAXNORM, nrm);
        suba  *= s;
        sub_sq = MAXNORM * MAXNORM;
    }

    const float lam = __fdividef(2.0f, fmaxf(1.0f - sub_sq, EPS32));
    const float arg = lam * suba * ranorm;

    float sc;
    if (fabsf(arg) < 16.0f) {
        sc = arg;  // smooth clamp is identity to <1e-14 here
    } else {
        const float z1  = SMOOTHB * (arg + CLAMP_V);
        const float z2  = SMOOTHB * (arg - CLAMP_V);
        const float sp1 = fmaxf(z1, 0.0f) + log1pf(__expf(-fabsf(z1)));
        const float sp2 = fmaxf(z2, 0.0f) + log1pf(__expf(-fabsf(z2)));
        sc = -CLAMP_V + (sp1 - sp2) * (1.0f / SMOOTHB);
    }

    const float s_ = fabsf(sc);
    const float r  = __logf(s_ + sqrtf(fmaf(s_, s_, 1.0f)));   // asinh(|sc|)
    return coef * copysignf(r, sc);
}

// ---------------- fused kernel ----------------
// grid (2, 64): ob = 64-output slice, bb = 64-batch tile. 512 threads = 16 warps.
// Prologue specialization: warps 0-3 A-split+vv, 4-11 B-split, 12-13 per-o constants.
// Mainloop: warp w -> m-tile (w&3)*16, n-quarter (w>>2)*16 (P and W).
__global__ __launch_bounds__(512, 1)
void hyp_mma_kernel(const float* __restrict__ x,
                    const float* __restrict__ w,
                    const float* __restrict__ p,
                    float* __restrict__ out) {
    extern __shared__ __align__(16) char sm[];
    const uint32_t sbase = smem_to_u32(sm);

    const int tid  = threadIdx.x;
    const int wid  = tid >> 5;
    const int lane = tid & 31;
    const int ob   = blockIdx.x;   // 0..1
    const int bb   = blockIdx.y;   // 0..63

    float* vvs = reinterpret_cast<float*>(sm + VVS_OFF);
    float* cU  = reinterpret_cast<float*>(sm + C_UU_OFF);
    float* cAs = reinterpret_cast<float*>(sm + C_AS_OFF);
    float* cUa = reinterpret_cast<float*>(sm + C_UA_OFF);
    float* cRn = reinterpret_cast<float*>(sm + C_RN_OFF);
    float* cCf = reinterpret_cast<float*>(sm + C_CF_OFF);

    if (tid < 128) {
        // ---- A: x tile [64][128], bf16-split, fused vv ----
        const int row = tid >> 1;        // 0..63
        const int q   = tid & 1;         // 64-col half
        const float* src = x + (size_t)(bb * 64 + row) * 128 + q * 64;
        char* hi = sm + A_HI_OFF;
        char* lo = sm + A_LO_OFF;
        float ss = 0.0f;
#pragma unroll
        for (int i = 0; i < 16; i++) {
            float4 v = reinterpret_cast<const float4*>(src)[i];
            ss += v.x * v.x + v.y * v.y + v.z * v.z + v.w * v.w;
            store_split8(hi, lo, (uint32_t)(row * 272 + (q * 64 + i * 4) * 2), v);
        }
        ss += __shfl_xor_sync(0xffffffffu, ss, 1);
        if (q == 0) vvs[row] = ss;
    } else if (tid < 384) {
        // ---- B: [p slice; w slice] [128][128], bf16-split ----
        const int idx = tid - 128;
        const int row = idx >> 1;        // 0..127
        const int q   = idx & 1;
        const float* src = (row < 64)
            ? (p + (size_t)(ob * 64 + row) * 128 + q * 64)
            : (w + (size_t)(ob * 64 + row - 64) * 128 + q * 64);
        char* hi = sm + B_HI_OFF;
        char* lo = sm + B_LO_OFF;
#pragma unroll
        for (int i = 0; i < 16; i++) {
            float4 v = reinterpret_cast<const float4*>(src)[i];
            store_split8(hi, lo, (uint32_t)(row * 272 + (q * 64 + i * 4) * 2), v);
        }
    } else if (tid < 448) {
        // ---- per-o constants: one thread per output, full 128-k dots ----
        const int ol = tid - 384;        // 0..63
        const int og = ob * 64 + ol;
        const float4* pr = reinterpret_cast<const float4*>(p + (size_t)og * 128);
        const float4* wr = reinterpret_cast<const float4*>(w + (size_t)og * 128);
        float pp = 0.0f, ww = 0.0f, pw = 0.0f;
        float pp1 = 0.0f, ww1 = 0.0f, pw1 = 0.0f;
#pragma unroll
        for (int i = 0; i < 32; i += 2) {
            float4 a = pr[i], b = wr[i];
            float4 a1 = pr[i + 1], b1 = wr[i + 1];
            pp  += a.x * a.x + a.y * a.y + a.z * a.z + a.w * a.w;
            ww  += b.x * b.x + b.y * b.y + b.z * b.z + b.w * b.w;
            pw  += a.x * b.x + a.y * b.y + a.z * b.z + a.w * b.w;
            pp1 += a1.x * a1.x + a1.y * a1.y + a1.z * a1.z + a1.w * a1.w;
            ww1 += b1.x * b1.x + b1.y * b1.y + b1.z * b1.z + b1.w * b1.w;
            pw1 += a1.x * b1.x + a1.y * b1.y + a1.z * b1.z + a1.w * b1.w;
        }
        pp += pp1; ww += ww1; pw += pw1;
        const float uu     = pp;
        const float ascale = fmaxf(1.0f - uu, EPS32);   // 2/lambda_bias
        const float anorm  = fmaxf(ascale * sqrtf(ww), MIN_ENORM);
        cU[ol]  = uu;
        cAs[ol] = ascale;
        cUa[ol] = -ascale * pw;
        cRn[ol] = 1.0f / anorm;
        cCf[ol] = (2.0f / fmaxf(1.0f - uu, EPS32)) * anorm;
    }
    __syncthreads();

    // ---- ldmatrix address prep ----
    const int mt   = wid & 3;              // m-tile (16 rows)
    const int nq   = (wid >> 2) * 16;      // n-quarter (16 outputs)
    const int r8   = (lane & 7) + ((lane >> 3) & 1) * 8;
    const int koff = (lane >> 4) * 8;
    const uint32_t aOff = (uint32_t)((mt * 16 + r8) * 272 + koff * 2);
    const uint32_t bpO  = (uint32_t)((nq + r8) * 272 + koff * 2);
    const uint32_t bwO  = (uint32_t)((nq + 64 + r8) * 272 + koff * 2);

    float accP[2][4], accW[2][4];
#pragma unroll
    for (int j = 0; j < 2; j++)
#pragma unroll
        for (int c = 0; c < 4; c++) { accP[j][c] = 0.0f; accW[j][c] = 0.0f; }

    // ---- mainloop: 3 split terms (hi*hi, hi*lo, lo*hi), 8 k-steps each ----
#pragma unroll
    for (int term = 0; term < 3; term++) {
        const uint32_t aBase = sbase + (term == 2 ? A_LO_OFF : A_HI_OFF);
        const uint32_t bBase = sbase + (term == 1 ? B_LO_OFF : B_HI_OFF);
#pragma unroll
        for (int ks = 0; ks < 8; ks++) {
            const uint32_t kb = (uint32_t)ks * 32u;
            uint32_t a[4], bp[4], bw4[4];
            ldsm4(aBase + aOff + kb, a);
            ldsm4(bBase + bpO + kb, bp);
            ldsm4(bBase + bwO + kb, bw4);
            mma16816(accP[0], a, bp[0], bp[2]);
            mma16816(accP[1], a, bp[1], bp[3]);
            mma16816(accW[0], a, bw4[0], bw4[2]);
            mma16816(accW[1], a, bw4[1], bw4[3]);
        }
    }

    // ---- epilogue: thread holds D rows m0, m0+8; cols q*2, q*2+1 per n8 tile ----
    {
        const int m0 = mt * 16 + (lane >> 2);
        const int q  = lane & 3;
        const float vv0 = vvs[m0];
        const float vv1 = vvs[m0 + 8];
        const size_t bG0 = (size_t)(bb * 64 + m0) * 128;
        const size_t bG1 = (size_t)(bb * 64 + m0 + 8) * 128;
#pragma unroll
        for (int j = 0; j < 2; j++) {
            const int ol0 = nq + j * 8 + q * 2;
            const int ol1 = ol0 + 1;
            const int og0 = ob * 64 + ol0;
            const float u0 = cU[ol0],  u1 = cU[ol1];
            const float s0 = cAs[ol0], s1 = cAs[ol1];
            const float a0 = cUa[ol0], a1 = cUa[ol1];
            const float r0 = cRn[ol0], r1 = cRn[ol1];
            const float f0 = cCf[ol0], f1 = cCf[ol1];

            float2 e0, e1;
            e0.x = epilogue(accP[j][0], accW[j][0], vv0, u0, s0, a0, r0, f0);
            e0.y = epilogue(accP[j][1], accW[j][1], vv0, u1, s1, a1, r1, f1);
            e1.x = epilogue(accP[j][2], accW[j][2], vv1, u0, s0, a0, r0, f0);
            e1.y = epilogue(accP[j][3], accW[j][3], vv1, u1, s1, a1, r1, f1);

            *reinterpret_cast<float2*>(out + bG0 + og0) = e0;
            *reinterpret_cast<float2*>(out + bG1 + og0) = e1;
        }
    }
}

extern "C" void kernel_launch(void* const* d_in, const int* in_sizes, int n_in,
                              void* d_out, int out_size) {
    const float* x = (const float*)d_in[0];   // [4096, 128]
    const float* w = (const float*)d_in[1];   // [128, 128] weight
    const float* p = (const float*)d_in[2];   // [128, 128] bias
    float* out = (float*)d_out;               // [4096, 128]

    cudaFuncSetAttribute(hyp_mma_kernel,
                         cudaFuncAttributeMaxDynamicSharedMemorySize, SMEM_BYTES);
    dim3 grid(2, 64);
    hyp_mma_kernel<<<grid, 512, SMEM_BYTES>>>(x, w, p, out);
}